// round 1
// baseline (speedup 1.0000x reference)
#include <cuda_runtime.h>
#include <math.h>

// ---------------- problem constants ----------------
#define BATCH   8192
#define TSTEPS  99
#define DIN     32
#define DH      100
#define DHP     112          // padded hidden (4 thread-slices of 28)
#define JT      28           // j per thread (7 float4)
#define GRP     4            // threads per row
#define RW      16
#define RU      25
#define RP      28           // padded rank for phase-1 accumulation
#define NCLS    6
#define ROWS_CTA 64
#define NTHREADS 256
#define NGRID   (BATCH / ROWS_CTA)   // 128

// ---------------- device-global prepped weights ----------------
__device__ float g_Wc [DIN * DHP];     // W1@W2, [k][j] row-major, zero-padded
__device__ float g_U1p[DHP * RP];      // slot-major: slot = jl*4+g  (j = g*28+jl)
__device__ float g_U2p[RU  * DHP];     // [r][j]
__device__ float g_bg [DHP];
__device__ float g_bu [DHP];
__device__ float g_sc [2];             // sigmoid(zeta), sigmoid(nu)

// ---------------- packed f32x2 FMA ----------------
__device__ __forceinline__ void fma2(float2& d, float2 a, float2 b) {
    asm("fma.rn.f32x2 %0, %1, %2, %0;"
        : "+l"(reinterpret_cast<unsigned long long&>(d))
        : "l"(reinterpret_cast<unsigned long long&>(a)),
          "l"(reinterpret_cast<unsigned long long&>(b)));
}

// ---------------- setup: pad / transpose / fold weights ----------------
__global__ void setup_kernel(const float* __restrict__ W1, const float* __restrict__ W2,
                             const float* __restrict__ U1, const float* __restrict__ U2,
                             const float* __restrict__ bg, const float* __restrict__ bu,
                             const float* __restrict__ zeta, const float* __restrict__ nu) {
    int tid = threadIdx.x;
    // Wc = W1 @ W2  (32 x 112, zero pad j>=100)
    for (int idx = tid; idx < DIN * DHP; idx += blockDim.x) {
        int k = idx / DHP, j = idx % DHP;
        float s = 0.f;
        if (j < DH)
            for (int r = 0; r < RW; r++) s = fmaf(W1[k * RW + r], W2[r * DH + j], s);
        g_Wc[idx] = s;
    }
    // U1p: slot = jl*4+g maps to original j = g*28+jl; cols padded to 28 (r>=25 -> 0)
    for (int idx = tid; idx < DHP * RP; idx += blockDim.x) {
        int slot = idx / RP, r = idx % RP;
        int jl = slot >> 2, g = slot & 3;
        int j = g * JT + jl;
        g_U1p[idx] = (j < DH && r < RU) ? U1[j * RU + r] : 0.f;
    }
    // U2p: [r][j] padded j
    for (int idx = tid; idx < RU * DHP; idx += blockDim.x) {
        int r = idx / DHP, j = idx % DHP;
        g_U2p[idx] = (j < DH) ? U2[r * DH + j] : 0.f;
    }
    for (int j = tid; j < DHP; j += blockDim.x) {
        g_bg[j] = (j < DH) ? bg[j] : 0.f;
        g_bu[j] = (j < DH) ? bu[j] : 0.f;
    }
    if (tid == 0) {
        g_sc[0] = 1.f / (1.f + expf(-zeta[0]));
        g_sc[1] = 1.f / (1.f + expf(-nu[0]));
    }
}

// ---------------- fused recurrent kernel ----------------
__global__ void __launch_bounds__(NTHREADS, 1)
grnn_kernel(const float* __restrict__ x, const float* __restrict__ FC,
            const float* __restrict__ FCb, float* __restrict__ out) {
    // static SMEM: 48192 bytes total
    __shared__ __align__(16) float U1s[DHP * RP];     // 3136
    __shared__ __align__(16) float U2s[RU * DHP];     // 2800
    __shared__ __align__(16) float Wcs[DIN * DHP];    // 3584
    __shared__ __align__(16) float bgs[DHP];
    __shared__ __align__(16) float bus[DHP];
    __shared__ __align__(16) float xs[ROWS_CTA * 36]; // padded stride 36 (bank-safe)

    const int tid = threadIdx.x;
    for (int i = tid; i < DHP * RP; i += NTHREADS) U1s[i] = g_U1p[i];
    for (int i = tid; i < RU * DHP; i += NTHREADS) U2s[i] = g_U2p[i];
    for (int i = tid; i < DIN * DHP; i += NTHREADS) Wcs[i] = g_Wc[i];
    for (int i = tid; i < DHP; i += NTHREADS) { bgs[i] = g_bg[i]; bus[i] = g_bu[i]; }

    const float sz = g_sc[0];
    const float sn = g_sc[1];

    const int g     = tid & 3;          // slice id within row
    const int rloc  = tid >> 2;         // local row 0..63
    const int row   = blockIdx.x * ROWS_CTA + rloc;
    const int jbase = g * JT;
    const float* xrow = x + (size_t)row * (TSTEPS * DIN);

    float2 H[JT / 2];
#pragma unroll
    for (int i = 0; i < JT / 2; i++) H[i] = make_float2(0.f, 0.f);

    // preload step 0 tile (coalesced: 4 lanes cover 128B/row)
    {
        float4 a = *(const float4*)(xrow + g * 8);
        float4 b = *(const float4*)(xrow + g * 8 + 4);
        float4* dst = (float4*)(xs + rloc * 36 + g * 8);
        dst[0] = a; dst[1] = b;
    }
    __syncthreads();

    for (int t = 0; t < TSTEPS; t++) {
        // prefetch next step's x into registers (harmless repeat on last step)
        const int tn = (t + 1 < TSTEPS) ? (t + 1) : t;
        float4 pa = *(const float4*)(xrow + tn * DIN + g * 8);
        float4 pb = *(const float4*)(xrow + tn * DIN + g * 8 + 4);

        // ---- phase 1: partial Hp = H_loc @ U1 ----
        float2 php[RP / 2];
#pragma unroll
        for (int i = 0; i < RP / 2; i++) php[i] = make_float2(0.f, 0.f);
#pragma unroll
        for (int jl = 0; jl < JT; jl++) {
            float hv = (jl & 1) ? H[jl >> 1].y : H[jl >> 1].x;
            float2 h2 = make_float2(hv, hv);
            const float4* urow = (const float4*)(U1s + (jl * 4 + g) * RP);
#pragma unroll
            for (int q = 0; q < 7; q++) {
                float4 u = urow[q];
                fma2(php[2 * q],     h2, make_float2(u.x, u.y));
                fma2(php[2 * q + 1], h2, make_float2(u.z, u.w));
            }
        }
        // ---- all-reduce Hp over the 4 lanes of this row ----
#pragma unroll
        for (int i = 0; i < RP / 2; i++) {
            float sx = php[i].x, sy = php[i].y;
            sx += __shfl_xor_sync(0xffffffffu, sx, 1);
            sy += __shfl_xor_sync(0xffffffffu, sy, 1);
            sx += __shfl_xor_sync(0xffffffffu, sx, 2);
            sy += __shfl_xor_sync(0xffffffffu, sy, 2);
            php[i] = make_float2(sx, sy);
        }

        // ---- phase 2: c = x@Wc + Hp@U2 on this thread's 28-wide slice ----
        float2 c[JT / 2];
#pragma unroll
        for (int i = 0; i < JT / 2; i++) c[i] = make_float2(0.f, 0.f);

        const float* xcur = xs + rloc * 36;
#pragma unroll
        for (int k4 = 0; k4 < 8; k4++) {
            float4 xv = *(const float4*)(xcur + k4 * 4);
#pragma unroll
            for (int e = 0; e < 4; e++) {
                float xk = (e == 0) ? xv.x : (e == 1) ? xv.y : (e == 2) ? xv.z : xv.w;
                float2 x2 = make_float2(xk, xk);
                const float4* wrow = (const float4*)(Wcs + (k4 * 4 + e) * DHP + jbase);
#pragma unroll
                for (int q = 0; q < 7; q++) {
                    float4 w = wrow[q];
                    fma2(c[2 * q],     x2, make_float2(w.x, w.y));
                    fma2(c[2 * q + 1], x2, make_float2(w.z, w.w));
                }
            }
        }
#pragma unroll
        for (int r = 0; r < RU; r++) {
            float hp = (r & 1) ? php[r >> 1].y : php[r >> 1].x;
            float2 h2 = make_float2(hp, hp);
            const float4* urow = (const float4*)(U2s + r * DHP + jbase);
#pragma unroll
            for (int q = 0; q < 7; q++) {
                float4 u = urow[q];
                fma2(c[2 * q],     h2, make_float2(u.x, u.y));
                fma2(c[2 * q + 1], h2, make_float2(u.z, u.w));
            }
        }

        // ---- elementwise gate/update ----
#pragma unroll
        for (int i = 0; i < JT / 2; i++) {
            int j = jbase + 2 * i;
            {
                float cc = c[i].x;
                float gg = __fdividef(1.f, 1.f + __expf(-(cc + bgs[j])));
                float hh = __fdividef(2.f, 1.f + __expf(-2.f * (cc + bus[j]))) - 1.f;
                H[i].x = fmaf(gg, H[i].x - sz, fmaf(sn, hh, sz));
            }
            {
                float cc = c[i].y;
                float gg = __fdividef(1.f, 1.f + __expf(-(cc + bgs[j + 1])));
                float hh = __fdividef(2.f, 1.f + __expf(-2.f * (cc + bus[j + 1]))) - 1.f;
                H[i].y = fmaf(gg, H[i].y - sz, fmaf(sn, hh, sz));
            }
        }

        // ---- publish next x tile (single buffer: drain readers first) ----
        __syncthreads();
        {
            float4* dst = (float4*)(xs + rloc * 36 + g * 8);
            dst[0] = pa; dst[1] = pb;
        }
        __syncthreads();
    }

    // ---- epilogue: score = H @ FC + FCbias ----
    float s[NCLS];
#pragma unroll
    for (int cix = 0; cix < NCLS; cix++) s[cix] = 0.f;
#pragma unroll
    for (int jl = 0; jl < JT; jl++) {
        int jg = jbase + jl;
        if (jg < DH) {
            float hv = (jl & 1) ? H[jl >> 1].y : H[jl >> 1].x;
#pragma unroll
            for (int cix = 0; cix < NCLS; cix++)
                s[cix] = fmaf(hv, FC[jg * NCLS + cix], s[cix]);
        }
    }
#pragma unroll
    for (int cix = 0; cix < NCLS; cix++) {
        s[cix] += __shfl_xor_sync(0xffffffffu, s[cix], 1);
        s[cix] += __shfl_xor_sync(0xffffffffu, s[cix], 2);
    }
    if (g == 0) {
#pragma unroll
        for (int cix = 0; cix < NCLS; cix++)
            out[row * NCLS + cix] = s[cix] + FCb[cix];
    }
}

// ---------------- launch ----------------
extern "C" void kernel_launch(void* const* d_in, const int* in_sizes, int n_in,
                              void* d_out, int out_size) {
    const float* x    = (const float*)d_in[0];
    const float* W1   = (const float*)d_in[1];
    const float* W2   = (const float*)d_in[2];
    const float* U1   = (const float*)d_in[3];
    const float* U2   = (const float*)d_in[4];
    const float* bg   = (const float*)d_in[5];
    const float* bu   = (const float*)d_in[6];
    const float* zeta = (const float*)d_in[7];
    const float* nu   = (const float*)d_in[8];
    const float* FC   = (const float*)d_in[9];
    const float* FCb  = (const float*)d_in[10];
    float* out = (float*)d_out;

    setup_kernel<<<1, 256>>>(W1, W2, U1, U2, bg, bu, zeta, nu);
    grnn_kernel<<<NGRID, NTHREADS>>>(x, FC, FCb, out);
}